// round 10
// baseline (speedup 1.0000x reference)
#include <cuda_runtime.h>
#include <cuda_fp16.h>
#include <cstdint>

#define N_ROWS 65536
#define DIM    256
#define KCODES 1024
#define CAP    32
#define M_COLLECT 4e-4f
#define M_KEEP    2e-4f
#define NP2    4096          // pass2 blocks (16 rows each)

__device__ float  g_znorm[N_ROWS];
__device__ float  g_enorm[KCODES];
__device__ __half g_zh[N_ROWS * DIM];
__device__ __half g_eh[KCODES * DIM];
__device__ float  g_rowmin[N_ROWS];
__device__ int    g_ccnt[N_ROWS];
__device__ float  g_cand_d[N_ROWS * CAP];
__device__ int    g_cand_i[N_ROWS * CAP];
__device__ double g_partial[NP2];
__device__ int    g_done;

// ---------------- pass1 smem layout ----------------
// As: 128 x 264 halfs (pitch 528B). Bs: 2 buffers x 128 x 264 halfs.
#define APITCH   264
#define TILE_B   (128 * APITCH * 2)     // 67584
#define SM_ZN    (3 * TILE_B)           // 512B
#define SM_EN    (SM_ZN + 512)          // 4096B
#define SM_MIN   (SM_EN + 4096)         // 512B
#define SM_CNT   (SM_MIN + 512)         // 512B
#define SMEM1    (SM_CNT + 512)         // 208384 B

__device__ __forceinline__ uint32_t smem_u32(const void* p) {
    uint32_t a;
    asm("{ .reg .u64 t; cvta.to.shared.u64 t, %1; cvt.u32.u64 %0, t; }" : "=r"(a) : "l"(p));
    return a;
}

// --------------------------------------------------------------------------
// Kernel 1: row norms + fp16 pre-conversion of z and embeddings.
// --------------------------------------------------------------------------
__global__ void norms_kernel(const float* __restrict__ z, const float* __restrict__ emb) {
    int w    = blockIdx.x * 8 + (threadIdx.x >> 5);
    int lane = threadIdx.x & 31;
    if (blockIdx.x == 0 && threadIdx.x == 0) g_done = 0;
    if (w >= N_ROWS + KCODES) return;
    const bool isz = (w < N_ROWS);
    const float* src = isz ? (z + (size_t)w * DIM) : (emb + (size_t)(w - N_ROWS) * DIM);
    float4 v1 = *(const float4*)(src + lane * 8);
    float4 v2 = *(const float4*)(src + lane * 8 + 4);
    float s = v1.x*v1.x + v1.y*v1.y + v1.z*v1.z + v1.w*v1.w
            + v2.x*v2.x + v2.y*v2.y + v2.z*v2.z + v2.w*v2.w;

    __half2 h0 = __floats2half2_rn(v1.x, v1.y);
    __half2 h1 = __floats2half2_rn(v1.z, v1.w);
    __half2 h2 = __floats2half2_rn(v2.x, v2.y);
    __half2 h3 = __floats2half2_rn(v2.z, v2.w);
    uint4 packed = make_uint4(*(uint32_t*)&h0, *(uint32_t*)&h1, *(uint32_t*)&h2, *(uint32_t*)&h3);
    __half* dsth = isz ? (g_zh + (size_t)w * DIM) : (g_eh + (size_t)(w - N_ROWS) * DIM);
    *(uint4*)(dsth + lane * 8) = packed;

    #pragma unroll
    for (int off = 16; off > 0; off >>= 1) s += __shfl_xor_sync(0xffffffffu, s, off);
    if (lane == 0) { if (isz) g_znorm[w] = s; else g_enorm[w - N_ROWS] = s; }
}

// --------------------------------------------------------------------------
// Pass 1: fp16 mma.sync (f32 accum) filter — R5 core, 2 syncs/tile,
// prefetch overlapped with the collect phase.
// CTA = 128 z-rows x all 1024 codes (8 tiles of 128). 512 threads, 16 warps,
// warp tile 32x32 (2 m x 4 n of m16n8k16).
// --------------------------------------------------------------------------
__device__ __forceinline__ void mma16816(float* d, const uint32_t* a, uint32_t b0, uint32_t b1) {
    asm volatile(
        "mma.sync.aligned.m16n8k16.row.col.f32.f16.f16.f32 "
        "{%0,%1,%2,%3}, {%4,%5,%6,%7}, {%8,%9}, {%0,%1,%2,%3};"
        : "+f"(d[0]), "+f"(d[1]), "+f"(d[2]), "+f"(d[3])
        : "r"(a[0]), "r"(a[1]), "r"(a[2]), "r"(a[3]), "r"(b0), "r"(b1));
}
#define LDM_X4(r0,r1,r2,r3,addr) \
    asm volatile("ldmatrix.sync.aligned.m8n8.x4.shared.b16 {%0,%1,%2,%3}, [%4];" \
                 : "=r"(r0), "=r"(r1), "=r"(r2), "=r"(r3) : "r"(addr))
#define CP16(dst, src) \
    asm volatile("cp.async.cg.shared.global [%0], [%1], 16;" :: "r"(dst), "l"(src))
#define CP_COMMIT() asm volatile("cp.async.commit_group;" ::: "memory")
#define CP_WAIT1()  asm volatile("cp.async.wait_group 1;"  ::: "memory")
#define CP_WAIT0()  asm volatile("cp.async.wait_group 0;"  ::: "memory")

__device__ __forceinline__ void load_tile16(uint32_t dstBase, const __half* src, int tid) {
    #pragma unroll
    for (int i = 0; i < 8; i++) {
        int c   = tid + i * 512;
        int row = c >> 5, col = c & 31;
        CP16(dstBase + row * (APITCH * 2) + col * 16, src + row * DIM + col * 8);
    }
}

__global__ __launch_bounds__(512, 1)
void pass1_kernel() {
    extern __shared__ char sm[];
    float* s_zn  = (float*)(sm + SM_ZN);
    float* s_en  = (float*)(sm + SM_EN);
    int*   s_min = (int*)(sm + SM_MIN);
    int*   s_cnt = (int*)(sm + SM_CNT);

    const int tid  = threadIdx.x;
    const int lane = tid & 31;
    const int warp = tid >> 5;
    const int wm   = warp & 3;
    const int wn   = warp >> 2;
    const int g    = lane >> 2;
    const int tg   = lane & 3;
    const int r0   = blockIdx.x * 128;

    const uint32_t sbA  = smem_u32(sm);
    const uint32_t sbB0 = sbA + TILE_B;

    uint32_t aAddr[2];
    #pragma unroll
    for (int mt = 0; mt < 2; mt++) {
        int rowA = 32 * wm + 16 * mt + ((lane >> 3) & 1) * 8 + (lane & 7);
        aAddr[mt] = sbA + rowA * (APITCH * 2) + (lane >> 4) * 16;
    }
    uint32_t bOff[2];
    #pragma unroll
    for (int p = 0; p < 2; p++) {
        int rowB = 32 * wn + 16 * p + ((lane >> 4) & 1) * 8 + (lane & 7);
        bOff[p] = rowB * (APITCH * 2) + ((lane >> 3) & 1) * 16;
    }

    // async prologue: A + B0 (group 0), B1 (group 1)
    load_tile16(sbA, g_zh + (size_t)r0 * DIM, tid);
    load_tile16(sbB0, g_eh, tid);
    CP_COMMIT();
    load_tile16(sbB0 + TILE_B, g_eh + 128 * DIM, tid);
    CP_COMMIT();

    if (tid < 128) {
        s_zn[tid]  = g_znorm[r0 + tid];
        s_min[tid] = 0x7F800000;
        s_cnt[tid] = 0;
    }
    #pragma unroll
    for (int i = 0; i < 2; i++) s_en[tid + i * 512] = g_enorm[tid + i * 512];

    CP_WAIT1();
    __syncthreads();

    float acc[2][4][4];
    #pragma unroll
    for (int mt = 0; mt < 2; mt++)
        #pragma unroll
        for (int nt = 0; nt < 4; nt++)
            #pragma unroll
            for (int e = 0; e < 4; e++) acc[mt][nt][e] = 0.0f;

    for (int ct = 0; ct < 8; ct++) {
        const uint32_t bbuf = sbB0 + (ct & 1) * TILE_B;

        // ---- k-loop: ldmatrix + mma ----
        #pragma unroll
        for (int ks = 0; ks < 16; ks++) {
            const uint32_t ko = ks * 32;
            uint32_t a0[4], a1[4], b0[4], b1[4];
            LDM_X4(a0[0], a0[1], a0[2], a0[3], aAddr[0] + ko);
            LDM_X4(a1[0], a1[1], a1[2], a1[3], aAddr[1] + ko);
            LDM_X4(b0[0], b0[1], b0[2], b0[3], bbuf + bOff[0] + ko);
            LDM_X4(b1[0], b1[1], b1[2], b1[3], bbuf + bOff[1] + ko);
            mma16816(acc[0][0], a0, b0[0], b0[1]);
            mma16816(acc[0][1], a0, b0[2], b0[3]);
            mma16816(acc[0][2], a0, b1[0], b1[1]);
            mma16816(acc[0][3], a0, b1[2], b1[3]);
            mma16816(acc[1][0], a1, b0[0], b0[1]);
            mma16816(acc[1][1], a1, b0[2], b0[3]);
            mma16816(acc[1][2], a1, b1[0], b1[1]);
            mma16816(acc[1][3], a1, b1[2], b1[3]);
        }

        // ---- min phase: distances + per-row running min ----
        #pragma unroll
        for (int mt = 0; mt < 2; mt++) {
            #pragma unroll
            for (int half_ = 0; half_ < 2; half_++) {
                const int r = 32 * wm + 16 * mt + g + 8 * half_;
                const float zn = s_zn[r];
                float rmin = 3.4e38f;
                #pragma unroll
                for (int nt = 0; nt < 4; nt++) {
                    const int c = ct * 128 + 32 * wn + 8 * nt + 2 * tg;
                    float d0 = (zn + s_en[c])     - 2.0f * acc[mt][nt][2 * half_];
                    float d1 = (zn + s_en[c + 1]) - 2.0f * acc[mt][nt][2 * half_ + 1];
                    rmin = fminf(rmin, fminf(d0, d1));
                }
                atomicMin(&s_min[r], __float_as_int(rmin));
            }
        }
        __syncthreads();   // sync1: all k-loops done (bbuf dead) + all mins posted

        // ---- prefetch next-next B tile NOW — overlaps the collect phase ----
        if (ct + 2 < 8) {
            load_tile16(sbB0 + (ct & 1) * TILE_B, g_eh + (size_t)(ct + 2) * 128 * DIM, tid);
            CP_COMMIT();
        }

        // ---- collect phase vs converged threshold (recompute from acc) ----
        #pragma unroll
        for (int mt = 0; mt < 2; mt++) {
            #pragma unroll
            for (int half_ = 0; half_ < 2; half_++) {
                const int r = 32 * wm + 16 * mt + g + 8 * half_;
                const float zn  = s_zn[r];
                const float thr = __int_as_float(s_min[r]) + M_COLLECT;
                #pragma unroll
                for (int nt = 0; nt < 4; nt++) {
                    const int c = ct * 128 + 32 * wn + 8 * nt + 2 * tg;
                    #pragma unroll
                    for (int e = 0; e < 2; e++) {
                        float dv = (zn + s_en[c + e]) - 2.0f * acc[mt][nt][2 * half_ + e];
                        if (dv <= thr) {
                            int p = atomicAdd(&s_cnt[r], 1);
                            if (p < CAP) {
                                size_t gi = (size_t)(r0 + r) * CAP + p;
                                g_cand_d[gi] = dv;
                                g_cand_i[gi] = c + e;
                            }
                        }
                        acc[mt][nt][2 * half_ + e] = 0.0f;
                    }
                }
            }
        }

        // ---- ensure next tile's B is resident, then release the tile ----
        if (ct + 2 < 8)      { CP_WAIT1(); }
        else if (ct + 1 < 8) { CP_WAIT0(); }
        __syncthreads();   // sync2
    }

    if (tid < 128) {
        g_rowmin[r0 + tid] = __int_as_float(s_min[tid]);
        g_ccnt[r0 + tid]   = s_cnt[tid];
    }
}

// --------------------------------------------------------------------------
// Pass 2: one warp per row — filter, rare exact fp32 rescore, gather, output,
// loss partial; last block finalizes the loss scalar.
// --------------------------------------------------------------------------
__device__ __forceinline__ float warp_sum(float v) {
    #pragma unroll
    for (int off = 16; off > 0; off >>= 1) v += __shfl_xor_sync(0xffffffffu, v, off);
    return v;
}

__global__ __launch_bounds__(512)
void pass2_kernel(const float* __restrict__ z, const float* __restrict__ emb,
                  float* __restrict__ out) {
    __shared__ float s_l[16];
    __shared__ double sd[512];
    __shared__ bool amLast;
    const int tid  = threadIdx.x;
    const int lane = tid & 31;
    const int row  = blockIdx.x * 16 + (tid >> 5);
    const float* zr = z + (size_t)row * DIM;
    const float4 z1 = *(const float4*)(zr + lane * 8);
    const float4 z2 = *(const float4*)(zr + lane * 8 + 4);
    const float zn = g_znorm[row];

    int widx;
    const int cnt = g_ccnt[row];
    if (cnt > CAP) {
        float bd = 3.4e38f; int bi = 0;
        for (int c = 0; c < KCODES; c++) {
            const float* er = emb + (size_t)c * DIM;
            float4 e1 = *(const float4*)(er + lane * 8);
            float4 e2 = *(const float4*)(er + lane * 8 + 4);
            float dot = z1.x*e1.x + z1.y*e1.y + z1.z*e1.z + z1.w*e1.w
                      + z2.x*e2.x + z2.y*e2.y + z2.z*e2.z + z2.w*e2.w;
            dot = warp_sum(dot);
            float d = (zn + g_enorm[c]) - 2.0f * dot;
            if (d < bd) { bd = d; bi = c; }
        }
        widx = bi;
    } else {
        const float vmin = g_rowmin[row];
        float cd = 3.4e38f; int ci = -1;
        if (lane < cnt) {
            cd = g_cand_d[(size_t)row * CAP + lane];
            ci = g_cand_i[(size_t)row * CAP + lane];
        }
        unsigned keep = __ballot_sync(0xffffffffu, cd <= vmin + M_KEEP);
        if (__popc(keep) == 1) {
            widx = __shfl_sync(0xffffffffu, ci, __ffs(keep) - 1);
        } else {
            float bd = 3.4e38f; int bi = 0x7fffffff;
            unsigned m = keep;
            while (m) {
                int src = __ffs(m) - 1; m &= m - 1;
                int c = __shfl_sync(0xffffffffu, ci, src);
                const float* er = emb + (size_t)c * DIM;
                float4 e1 = *(const float4*)(er + lane * 8);
                float4 e2 = *(const float4*)(er + lane * 8 + 4);
                float dot = z1.x*e1.x + z1.y*e1.y + z1.z*e1.z + z1.w*e1.w
                          + z2.x*e2.x + z2.y*e2.y + z2.z*e2.z + z2.w*e2.w;
                dot = warp_sum(dot);
                float d = (zn + g_enorm[c]) - 2.0f * dot;
                if (d < bd || (d == bd && c < bi)) { bd = d; bi = c; }
            }
            widx = bi;
        }
    }

    const float* er = emb + (size_t)widx * DIM;
    float4 e1 = *(const float4*)(er + lane * 8);
    float4 e2 = *(const float4*)(er + lane * 8 + 4);
    float d0 = e1.x - z1.x, d1 = e1.y - z1.y, d2 = e1.z - z1.z, d3 = e1.w - z1.w;
    float d4 = e2.x - z2.x, d5 = e2.y - z2.y, d6 = e2.z - z2.z, d7 = e2.w - z2.w;
    float4 o1 = make_float4(z1.x + d0, z1.y + d1, z1.z + d2, z1.w + d3);
    float4 o2 = make_float4(z2.x + d4, z2.y + d5, z2.z + d6, z2.w + d7);
    *(float4*)(out + (size_t)row * DIM + lane * 8)     = o1;
    *(float4*)(out + (size_t)row * DIM + lane * 8 + 4) = o2;
    float lsum = d0*d0 + d1*d1 + d2*d2 + d3*d3 + d4*d4 + d5*d5 + d6*d6 + d7*d7;
    lsum = warp_sum(lsum);
    if (lane == 0) s_l[tid >> 5] = lsum;
    __syncthreads();
    if (tid == 0) {
        double acc = 0.0;
        #pragma unroll
        for (int i = 0; i < 16; i++) acc += (double)s_l[i];
        g_partial[blockIdx.x] = acc;
        __threadfence();
        amLast = (atomicAdd(&g_done, 1) == NP2 - 1);
    }
    __syncthreads();

    if (amLast) {
        double a = 0.0;
        #pragma unroll
        for (int i = 0; i < NP2 / 512; i++) a += g_partial[tid + i * 512];
        sd[tid] = a;
        __syncthreads();
        for (int st = 256; st > 0; st >>= 1) {
            if (tid < st) sd[tid] += sd[tid + st];
            __syncthreads();
        }
        if (tid == 0) {
            float m = (float)(sd[0] / ((double)N_ROWS * (double)DIM));
            out[(size_t)N_ROWS * DIM] = m + 0.25f * m;
        }
    }
}

extern "C" void kernel_launch(void* const* d_in, const int* in_sizes, int n_in,
                              void* d_out, int out_size) {
    const float* z   = (const float*)d_in[0];
    const float* emb = (const float*)d_in[1];
    float* out = (float*)d_out;

    static int cfg_done = 0;
    if (!cfg_done) {
        cudaFuncSetAttribute(pass1_kernel, cudaFuncAttributeMaxDynamicSharedMemorySize, SMEM1);
        cfg_done = 1;
    }

    norms_kernel<<<(N_ROWS + KCODES) / 8, 256>>>(z, emb);
    pass1_kernel<<<N_ROWS / 128, 512, SMEM1>>>();
    pass2_kernel<<<NP2, 512>>>(z, emb, out);
}

// round 11
// speedup vs baseline: 1.0633x; 1.0633x over previous
#include <cuda_runtime.h>
#include <cuda_fp16.h>
#include <cstdint>

#define N_ROWS 65536
#define DIM    256
#define KCODES 1024
#define CAP    32
#define M_COLLECT 4e-4f
#define M_KEEP    2e-4f
#define NT     16            // code tiles of 64
#define NP2    4096          // pass2 blocks (16 rows each)

__device__ float  g_znorm[N_ROWS];
__device__ float  g_enorm[KCODES];
__device__ __half g_zh[N_ROWS * DIM];
__device__ __half g_eh[KCODES * DIM];
__device__ float  g_rowmin[N_ROWS];
__device__ int    g_ccnt[N_ROWS];
__device__ float  g_cand_d[N_ROWS * CAP];
__device__ int    g_cand_i[N_ROWS * CAP];
__device__ double g_partial[NP2];
__device__ int    g_done;

// ---------------- pass1 smem layout (fits 2 CTAs/SM) ----------------
// A: 128 x 264 halfs (pitch 528B) = 67584. B: ONE buffer, 64 x 264 halfs = 33792.
#define APITCH   264
#define TILE_A   (128 * APITCH * 2)     // 67584
#define TILE_B   (64 * APITCH * 2)      // 33792
#define SM_ZN    (TILE_A + TILE_B)      // 101376
#define SM_EN    (SM_ZN + 512)
#define SM_MIN   (SM_EN + 4096)
#define SM_CNT   (SM_MIN + 512)
#define SMEM1    (SM_CNT + 512)         // 107008 B  -> 2 CTAs/SM

__device__ __forceinline__ uint32_t smem_u32(const void* p) {
    uint32_t a;
    asm("{ .reg .u64 t; cvta.to.shared.u64 t, %1; cvt.u32.u64 %0, t; }" : "=r"(a) : "l"(p));
    return a;
}

// --------------------------------------------------------------------------
// Kernel 1: row norms + fp16 pre-conversion of z and embeddings.
// --------------------------------------------------------------------------
__global__ void norms_kernel(const float* __restrict__ z, const float* __restrict__ emb) {
    int w    = blockIdx.x * 8 + (threadIdx.x >> 5);
    int lane = threadIdx.x & 31;
    if (blockIdx.x == 0 && threadIdx.x == 0) g_done = 0;
    if (w >= N_ROWS + KCODES) return;
    const bool isz = (w < N_ROWS);
    const float* src = isz ? (z + (size_t)w * DIM) : (emb + (size_t)(w - N_ROWS) * DIM);
    float4 v1 = *(const float4*)(src + lane * 8);
    float4 v2 = *(const float4*)(src + lane * 8 + 4);
    float s = v1.x*v1.x + v1.y*v1.y + v1.z*v1.z + v1.w*v1.w
            + v2.x*v2.x + v2.y*v2.y + v2.z*v2.z + v2.w*v2.w;

    __half2 h0 = __floats2half2_rn(v1.x, v1.y);
    __half2 h1 = __floats2half2_rn(v1.z, v1.w);
    __half2 h2 = __floats2half2_rn(v2.x, v2.y);
    __half2 h3 = __floats2half2_rn(v2.z, v2.w);
    uint4 packed = make_uint4(*(uint32_t*)&h0, *(uint32_t*)&h1, *(uint32_t*)&h2, *(uint32_t*)&h3);
    __half* dsth = isz ? (g_zh + (size_t)w * DIM) : (g_eh + (size_t)(w - N_ROWS) * DIM);
    *(uint4*)(dsth + lane * 8) = packed;

    #pragma unroll
    for (int off = 16; off > 0; off >>= 1) s += __shfl_xor_sync(0xffffffffu, s, off);
    if (lane == 0) { if (isz) g_znorm[w] = s; else g_enorm[w - N_ROWS] = s; }
}

// --------------------------------------------------------------------------
// Pass 1: fp16 mma.sync (f32 accum) filter — R5 fragment layout, retiled to
// 107 KB smem so 2 CTAs co-reside per SM (epilogues/barriers hidden by the
// partner CTA's k-loop). 256 threads, 8 warps (4m x 2n), warp tile 32x32.
// CTA = 128 z-rows x 1024 codes in 16 tiles of 64, single B buffer.
// --------------------------------------------------------------------------
__device__ __forceinline__ void mma16816(float* d, const uint32_t* a, uint32_t b0, uint32_t b1) {
    asm volatile(
        "mma.sync.aligned.m16n8k16.row.col.f32.f16.f16.f32 "
        "{%0,%1,%2,%3}, {%4,%5,%6,%7}, {%8,%9}, {%0,%1,%2,%3};"
        : "+f"(d[0]), "+f"(d[1]), "+f"(d[2]), "+f"(d[3])
        : "r"(a[0]), "r"(a[1]), "r"(a[2]), "r"(a[3]), "r"(b0), "r"(b1));
}
#define LDM_X4(r0,r1,r2,r3,addr) \
    asm volatile("ldmatrix.sync.aligned.m8n8.x4.shared.b16 {%0,%1,%2,%3}, [%4];" \
                 : "=r"(r0), "=r"(r1), "=r"(r2), "=r"(r3) : "r"(addr))
#define CP16(dst, src) \
    asm volatile("cp.async.cg.shared.global [%0], [%1], 16;" :: "r"(dst), "l"(src))
#define CP_COMMIT() asm volatile("cp.async.commit_group;" ::: "memory")
#define CP_WAIT0()  asm volatile("cp.async.wait_group 0;"  ::: "memory")

__global__ __launch_bounds__(256, 2)
void pass1_kernel() {
    extern __shared__ char sm[];
    float* s_zn  = (float*)(sm + SM_ZN);
    float* s_en  = (float*)(sm + SM_EN);
    int*   s_min = (int*)(sm + SM_MIN);
    int*   s_cnt = (int*)(sm + SM_CNT);

    const int tid  = threadIdx.x;
    const int lane = tid & 31;
    const int warp = tid >> 5;      // 0..7
    const int wm   = warp & 3;      // row block
    const int wn   = warp >> 2;     // code block (0..1)
    const int g    = lane >> 2;
    const int tg   = lane & 3;
    const int r0   = blockIdx.x * 128;

    const uint32_t sbA = smem_u32(sm);
    const uint32_t sbB = sbA + TILE_A;

    // per-lane ldmatrix base addresses (identical fragment math to R5)
    uint32_t aAddr[2];
    #pragma unroll
    for (int mt = 0; mt < 2; mt++) {
        int rowA = 32 * wm + 16 * mt + ((lane >> 3) & 1) * 8 + (lane & 7);
        aAddr[mt] = sbA + rowA * (APITCH * 2) + (lane >> 4) * 16;
    }
    uint32_t bOff[2];
    #pragma unroll
    for (int p = 0; p < 2; p++) {
        int rowB = 32 * wn + 16 * p + ((lane >> 4) & 1) * 8 + (lane & 7);
        bOff[p] = rowB * (APITCH * 2) + ((lane >> 3) & 1) * 16;
    }

    // prologue: A tile (128 rows) + B tile 0 (64 rows), one cp.async group
    #pragma unroll
    for (int i = 0; i < 16; i++) {
        int c = tid + i * 256, row = c >> 5, col = c & 31;
        CP16(sbA + row * (APITCH * 2) + col * 16, g_zh + (size_t)(r0 + row) * DIM + col * 8);
    }
    #pragma unroll
    for (int i = 0; i < 8; i++) {
        int c = tid + i * 256, row = c >> 5, col = c & 31;
        CP16(sbB + row * (APITCH * 2) + col * 16, g_eh + (size_t)row * DIM + col * 8);
    }
    CP_COMMIT();

    if (tid < 128) {
        s_zn[tid]  = g_znorm[r0 + tid];
        s_min[tid] = 0x7F800000;
        s_cnt[tid] = 0;
    }
    #pragma unroll
    for (int i = 0; i < 4; i++) s_en[tid + i * 256] = g_enorm[tid + i * 256];

    CP_WAIT0();
    __syncthreads();

    float acc[2][4][4];
    #pragma unroll
    for (int mt = 0; mt < 2; mt++)
        #pragma unroll
        for (int nt = 0; nt < 4; nt++)
            #pragma unroll
            for (int e = 0; e < 4; e++) acc[mt][nt][e] = 0.0f;

    for (int ct = 0; ct < NT; ct++) {
        // ---- k-loop: ldmatrix + f32-accum mma (R5 body, fixed B buffer) ----
        #pragma unroll
        for (int ks = 0; ks < 16; ks++) {
            const uint32_t ko = ks * 32;
            uint32_t a0[4], a1[4], b0[4], b1[4];
            LDM_X4(a0[0], a0[1], a0[2], a0[3], aAddr[0] + ko);
            LDM_X4(a1[0], a1[1], a1[2], a1[3], aAddr[1] + ko);
            LDM_X4(b0[0], b0[1], b0[2], b0[3], sbB + bOff[0] + ko);
            LDM_X4(b1[0], b1[1], b1[2], b1[3], sbB + bOff[1] + ko);
            mma16816(acc[0][0], a0, b0[0], b0[1]);
            mma16816(acc[0][1], a0, b0[2], b0[3]);
            mma16816(acc[0][2], a0, b1[0], b1[1]);
            mma16816(acc[0][3], a0, b1[2], b1[3]);
            mma16816(acc[1][0], a1, b0[0], b0[1]);
            mma16816(acc[1][1], a1, b0[2], b0[3]);
            mma16816(acc[1][2], a1, b1[0], b1[1]);
            mma16816(acc[1][3], a1, b1[2], b1[3]);
        }

        // ---- min phase: distances + per-row running min ----
        #pragma unroll
        for (int mt = 0; mt < 2; mt++) {
            #pragma unroll
            for (int half_ = 0; half_ < 2; half_++) {
                const int r = 32 * wm + 16 * mt + g + 8 * half_;
                const float zn = s_zn[r];
                float rmin = 3.4e38f;
                #pragma unroll
                for (int nt = 0; nt < 4; nt++) {
                    const int c = ct * 64 + 32 * wn + 8 * nt + 2 * tg;
                    float d0 = (zn + s_en[c])     - 2.0f * acc[mt][nt][2 * half_];
                    float d1 = (zn + s_en[c + 1]) - 2.0f * acc[mt][nt][2 * half_ + 1];
                    rmin = fminf(rmin, fminf(d0, d1));
                }
                atomicMin(&s_min[r], __float_as_int(rmin));
            }
        }
        __syncthreads();   // all k-loops done (B buffer dead) + all mins posted

        // ---- issue next B tile into the freed buffer (overlaps collect) ----
        if (ct + 1 < NT) {
            #pragma unroll
            for (int i = 0; i < 8; i++) {
                int c = tid + i * 256, row = c >> 5, col = c & 31;
                CP16(sbB + row * (APITCH * 2) + col * 16,
                     g_eh + (size_t)((ct + 1) * 64 + row) * DIM + col * 8);
            }
            CP_COMMIT();
        }

        // ---- collect phase vs converged threshold (registers + s_min only) ----
        #pragma unroll
        for (int mt = 0; mt < 2; mt++) {
            #pragma unroll
            for (int half_ = 0; half_ < 2; half_++) {
                const int r = 32 * wm + 16 * mt + g + 8 * half_;
                const float zn  = s_zn[r];
                const float thr = __int_as_float(s_min[r]) + M_COLLECT;
                #pragma unroll
                for (int nt = 0; nt < 4; nt++) {
                    const int c = ct * 64 + 32 * wn + 8 * nt + 2 * tg;
                    #pragma unroll
                    for (int e = 0; e < 2; e++) {
                        float dv = (zn + s_en[c + e]) - 2.0f * acc[mt][nt][2 * half_ + e];
                        if (dv <= thr) {
                            int p = atomicAdd(&s_cnt[r], 1);
                            if (p < CAP) {
                                size_t gi = (size_t)(r0 + r) * CAP + p;
                                g_cand_d[gi] = dv;
                                g_cand_i[gi] = c + e;
                            }
                        }
                        acc[mt][nt][2 * half_ + e] = 0.0f;
                    }
                }
            }
        }

        CP_WAIT0();
        __syncthreads();
    }

    if (tid < 128) {
        g_rowmin[r0 + tid] = __int_as_float(s_min[tid]);
        g_ccnt[r0 + tid]   = s_cnt[tid];
    }
}

// --------------------------------------------------------------------------
// Pass 2: one warp per row — filter, rare exact fp32 rescore, gather, output,
// loss partial; last block finalizes the loss scalar.
// --------------------------------------------------------------------------
__device__ __forceinline__ float warp_sum(float v) {
    #pragma unroll
    for (int off = 16; off > 0; off >>= 1) v += __shfl_xor_sync(0xffffffffu, v, off);
    return v;
}

__global__ __launch_bounds__(512)
void pass2_kernel(const float* __restrict__ z, const float* __restrict__ emb,
                  float* __restrict__ out) {
    __shared__ float s_l[16];
    __shared__ double sd[512];
    __shared__ bool amLast;
    const int tid  = threadIdx.x;
    const int lane = tid & 31;
    const int row  = blockIdx.x * 16 + (tid >> 5);
    const float* zr = z + (size_t)row * DIM;
    const float4 z1 = *(const float4*)(zr + lane * 8);
    const float4 z2 = *(const float4*)(zr + lane * 8 + 4);
    const float zn = g_znorm[row];

    int widx;
    const int cnt = g_ccnt[row];
    if (cnt > CAP) {
        float bd = 3.4e38f; int bi = 0;
        for (int c = 0; c < KCODES; c++) {
            const float* er = emb + (size_t)c * DIM;
            float4 e1 = *(const float4*)(er + lane * 8);
            float4 e2 = *(const float4*)(er + lane * 8 + 4);
            float dot = z1.x*e1.x + z1.y*e1.y + z1.z*e1.z + z1.w*e1.w
                      + z2.x*e2.x + z2.y*e2.y + z2.z*e2.z + z2.w*e2.w;
            dot = warp_sum(dot);
            float d = (zn + g_enorm[c]) - 2.0f * dot;
            if (d < bd) { bd = d; bi = c; }
        }
        widx = bi;
    } else {
        const float vmin = g_rowmin[row];
        float cd = 3.4e38f; int ci = -1;
        if (lane < cnt) {
            cd = g_cand_d[(size_t)row * CAP + lane];
            ci = g_cand_i[(size_t)row * CAP + lane];
        }
        unsigned keep = __ballot_sync(0xffffffffu, cd <= vmin + M_KEEP);
        if (__popc(keep) == 1) {
            widx = __shfl_sync(0xffffffffu, ci, __ffs(keep) - 1);
        } else {
            float bd = 3.4e38f; int bi = 0x7fffffff;
            unsigned m = keep;
            while (m) {
                int src = __ffs(m) - 1; m &= m - 1;
                int c = __shfl_sync(0xffffffffu, ci, src);
                const float* er = emb + (size_t)c * DIM;
                float4 e1 = *(const float4*)(er + lane * 8);
                float4 e2 = *(const float4*)(er + lane * 8 + 4);
                float dot = z1.x*e1.x + z1.y*e1.y + z1.z*e1.z + z1.w*e1.w
                          + z2.x*e2.x + z2.y*e2.y + z2.z*e2.z + z2.w*e2.w;
                dot = warp_sum(dot);
                float d = (zn + g_enorm[c]) - 2.0f * dot;
                if (d < bd || (d == bd && c < bi)) { bd = d; bi = c; }
            }
            widx = bi;
        }
    }

    const float* er = emb + (size_t)widx * DIM;
    float4 e1 = *(const float4*)(er + lane * 8);
    float4 e2 = *(const float4*)(er + lane * 8 + 4);
    float d0 = e1.x - z1.x, d1 = e1.y - z1.y, d2 = e1.z - z1.z, d3 = e1.w - z1.w;
    float d4 = e2.x - z2.x, d5 = e2.y - z2.y, d6 = e2.z - z2.z, d7 = e2.w - z2.w;
    float4 o1 = make_float4(z1.x + d0, z1.y + d1, z1.z + d2, z1.w + d3);
    float4 o2 = make_float4(z2.x + d4, z2.y + d5, z2.z + d6, z2.w + d7);
    *(float4*)(out + (size_t)row * DIM + lane * 8)     = o1;
    *(float4*)(out + (size_t)row * DIM + lane * 8 + 4) = o2;
    float lsum = d0*d0 + d1*d1 + d2*d2 + d3*d3 + d4*d4 + d5*d5 + d6*d6 + d7*d7;
    lsum = warp_sum(lsum);
    if (lane == 0) s_l[tid >> 5] = lsum;
    __syncthreads();
    if (tid == 0) {
        double acc = 0.0;
        #pragma unroll
        for (int i = 0; i < 16; i++) acc += (double)s_l[i];
        g_partial[blockIdx.x] = acc;
        __threadfence();
        amLast = (atomicAdd(&g_done, 1) == NP2 - 1);
    }
    __syncthreads();

    if (amLast) {
        double a = 0.0;
        #pragma unroll
        for (int i = 0; i < NP2 / 512; i++) a += g_partial[tid + i * 512];
        sd[tid] = a;
        __syncthreads();
        for (int st = 256; st > 0; st >>= 1) {
            if (tid < st) sd[tid] += sd[tid + st];
            __syncthreads();
        }
        if (tid == 0) {
            float m = (float)(sd[0] / ((double)N_ROWS * (double)DIM));
            out[(size_t)N_ROWS * DIM] = m + 0.25f * m;
        }
    }
}

extern "C" void kernel_launch(void* const* d_in, const int* in_sizes, int n_in,
                              void* d_out, int out_size) {
    const float* z   = (const float*)d_in[0];
    const float* emb = (const float*)d_in[1];
    float* out = (float*)d_out;

    static int cfg_done = 0;
    if (!cfg_done) {
        cudaFuncSetAttribute(pass1_kernel, cudaFuncAttributeMaxDynamicSharedMemorySize, SMEM1);
        cfg_done = 1;
    }

    norms_kernel<<<(N_ROWS + KCODES) / 8, 256>>>(z, emb);
    pass1_kernel<<<N_ROWS / 128, 256, SMEM1>>>();
    pass2_kernel<<<NP2, 512>>>(z, emb, out);
}